// round 11
// baseline (speedup 1.0000x reference)
#include <cuda_runtime.h>

// Problem constants
#define Bn  16
#define Cn  32
#define Nn  128
#define Tn  12
#define COn 64
#define NT  (Nn * Tn)          // 1536 floats per (b,i,j) row of A
#define NT4 (NT / 4)           // 384 float4
#define NSLICE (Bn * Cn)       // 512 (b,i) slices

// prop config: 128 persistent CTAs (1 CTA/SM via smem size), 768 threads =
// 4 groups x 192; group g streams j-rows [32g, 32g+32).
#define PROP_CTAS    128
#define PROP_THREADS 768
#define NGRP 4
#define GSZ  192
#define JPG  (Nn / NGRP)       // 32
#define JNC  24                // rows per group read twice from gmem
#define JC   8                 // rows per group cached in smem for pass 2
#define CACHE_BYTES (NGRP * JC * NT4 * 16)   // 196608 = 192 KB dynamic

// Scratch: h = concat([x1, x2], channel axis) -> [B][2C][N*T] = 6.3 MB
__device__ float g_h[(size_t)Bn * 2 * Cn * NT];

extern __shared__ float4 acache[];   // [NGRP][JC][NT4]

__device__ __forceinline__ void fma4(float4& acc, const float4 a, const float4 v) {
    acc.x = fmaf(a.x, v.x, acc.x);
    acc.y = fmaf(a.y, v.y, acc.y);
    acc.z = fmaf(a.z, v.z, acc.z);
    acc.w = fmaf(a.w, v.w, acc.w);
}
__device__ __forceinline__ float4 add4(const float4 a, const float4 b) {
    return make_float4(a.x + b.x, a.y + b.y, a.z + b.z, a.w + b.w);
}

// ---------------------------------------------------------------------------
// Kernel 1: fused order-1 + order-2 propagation (R3 structure) + pass-2
// smem cache. Pass 1: rows 0..23 use the exact R3 unroll-8 stream; rows
// 24..31 are staged through registers, stored to the 192KB smem cache, and
// accumulated. Pass 2: rows 0..23 from L2 (phase-locked footprint
// 128x786KB=100MB <= 126MB, proven), rows 24..31 from smem -> 25% fewer
// pass-2 gmem bytes. part[] covers only groups 0-2; group 3 keeps partials
// in registers and performs both reductions (frees 6KB static smem).
// ---------------------------------------------------------------------------
__global__ __launch_bounds__(PROP_THREADS, 1)
void prop_kernel(const float* __restrict__ x, const float* __restrict__ A) {
    __shared__ float4 part[NGRP - 1][NT4];   // 18 KB: partials of groups 0-2
    __shared__ float4 xs[NT4];               // x slice,  [j*3 + lq]
    __shared__ float4 x1s[NT4];              // x1 slice, same layout

    const int t  = threadIdx.x;
    const int g  = t / GSZ;
    const int ti = t - g * GSZ;              // 0..191
    const int lq = ti % 3;
    const int j0 = g * JPG;
    float4* cache = acache + (size_t)g * JC * NT4;

    for (int bc = blockIdx.x; bc < NSLICE; bc += PROP_CTAS) {
        const float4* __restrict__ xp = (const float4*)(x + (size_t)bc * NT);
        const float4* __restrict__ Ap = (const float4*)(A + (size_t)bc * Nn * NT);
        const int b = bc / Cn;
        const int i = bc % Cn;
        float4* hrow1 = (float4*)(g_h + ((size_t)b * 2 * Cn + i) * NT);
        float4* hrow2 = (float4*)(g_h + ((size_t)b * 2 * Cn + Cn + i) * NT);

        if (t < NT4) xs[t] = xp[t];
        __syncthreads();   // also the end-of-previous-iteration barrier

        // ---- Pass 1, rows 0..23: exact R3 streaming loop
        float4 acc0 = make_float4(0.f, 0.f, 0.f, 0.f);
        float4 acc1 = make_float4(0.f, 0.f, 0.f, 0.f);
        const float4* __restrict__ ap = Ap + (size_t)j0 * NT4;
#pragma unroll 8
        for (int jj = 0; jj < JNC; ++jj) {
            float4 a0 = ap[jj * NT4 + ti];
            float4 a1 = ap[jj * NT4 + ti + GSZ];
            float4 xv = xs[(j0 + jj) * 3 + lq];
            fma4(acc0, a0, xv);
            fma4(acc1, a1, xv);
        }
        // ---- Pass 1, rows 24..31: stage 2 rows at a time, STS to cache, FMA
#pragma unroll
        for (int jc = 0; jc < JC / 2; ++jc) {
            const int j1 = JNC + 2 * jc;
            float4 a0 = ap[j1 * NT4 + ti];
            float4 a1 = ap[j1 * NT4 + ti + GSZ];
            float4 b0 = ap[(j1 + 1) * NT4 + ti];
            float4 b1 = ap[(j1 + 1) * NT4 + ti + GSZ];
            float4* cc = cache + (size_t)(2 * jc) * NT4;
            cc[ti]             = a0;
            cc[ti + GSZ]       = a1;
            cc[NT4 + ti]       = b0;
            cc[NT4 + ti + GSZ] = b1;
            float4 xv0 = xs[(j0 + j1) * 3 + lq];
            float4 xv1 = xs[(j0 + j1 + 1) * 3 + lq];
            fma4(acc0, a0, xv0);
            fma4(acc1, a1, xv0);
            fma4(acc0, b0, xv1);
            fma4(acc1, b1, xv1);
        }
        if (g < NGRP - 1) {
            part[g][ti]       = acc0;
            part[g][ti + GSZ] = acc1;
        }
        __syncthreads();

        // ---- Reduce 1 (group 3 threads): x1 = part0+part1+part2+own regs
        if (g == NGRP - 1) {
            float4 ra = add4(add4(part[0][ti], part[1][ti]),
                             add4(part[2][ti], acc0));
            float4 rb = add4(add4(part[0][ti + GSZ], part[1][ti + GSZ]),
                             add4(part[2][ti + GSZ], acc1));
            x1s[ti]         = ra;
            x1s[ti + GSZ]   = rb;
            hrow1[ti]       = ra;    // h x1 row written immediately
            hrow1[ti + GSZ] = rb;
        }
        __syncthreads();

        // ---- Pass 2, rows 0..23: L2 re-read (R3 loop)
        acc0 = make_float4(0.f, 0.f, 0.f, 0.f);
        acc1 = make_float4(0.f, 0.f, 0.f, 0.f);
#pragma unroll 8
        for (int jj = 0; jj < JNC; ++jj) {
            float4 a0 = __ldlu(&ap[jj * NT4 + ti]);
            float4 a1 = __ldlu(&ap[jj * NT4 + ti + GSZ]);
            float4 xv = x1s[(j0 + jj) * 3 + lq];
            fma4(acc0, a0, xv);
            fma4(acc1, a1, xv);
        }
        // ---- Pass 2, rows 24..31: from smem cache
#pragma unroll
        for (int jj = JNC; jj < JPG; ++jj) {
            const float4* cc = cache + (size_t)(jj - JNC) * NT4;
            float4 xv = x1s[(j0 + jj) * 3 + lq];
            fma4(acc0, cc[ti], xv);
            fma4(acc1, cc[ti + GSZ], xv);
        }
        if (g < NGRP - 1) {
            part[g][ti]       = acc0;
            part[g][ti + GSZ] = acc1;
        }
        __syncthreads();

        // ---- Reduce 2 (group 3) + write h x2 row
        if (g == NGRP - 1) {
            float4 ra = add4(add4(part[0][ti], part[1][ti]),
                             add4(part[2][ti], acc0));
            float4 rb = add4(add4(part[0][ti + GSZ], part[1][ti + GSZ]),
                             add4(part[2][ti + GSZ], acc1));
            hrow2[ti]       = ra;
            hrow2[ti + GSZ] = rb;
        }
    }
}

// ---------------------------------------------------------------------------
// Kernel 2: 1x1 conv channel mix, smem-tiled GEMM with TRANSPOSED W.
// Inner loop per c: 1 LDS.128 (hv) + 1 LDS.128 (4 w's) + 16 FFMA = 18 instr
// (was 23) -> issue-bound time drops ~22%. Wt stride 68 floats keeps float4
// alignment (68 % 4 == 0) and spreads build-time bank conflicts.
// Block: 256 threads, tile = 64 outs x 64 cols, thread = 4 outs x 4 cols.
// ---------------------------------------------------------------------------
#define MIX_COLS 64
#define MIX_NCB  (NT / MIX_COLS)   // 24
#define WSTR     68

__global__ __launch_bounds__(256) void mix_kernel(const float* __restrict__ W,
                                                  const float* __restrict__ bias,
                                                  float* __restrict__ out) {
    __shared__ float4 hs[(2 * Cn) * (MIX_COLS / 4)];   // 16 KB
    __shared__ float  Wt[2 * Cn * WSTR];               // [c][o] 17 KB
    __shared__ float  bs[COn];

    const int t    = threadIdx.x;
    const int b    = blockIdx.x / MIX_NCB;
    const int col0 = (blockIdx.x % MIX_NCB) * MIX_COLS;
    const int colq = t & 15;
    const int oq   = t >> 4;

    // Build transposed W: coalesced float4 reads, scattered padded writes
    {
        const float4* W4 = (const float4*)W;
#pragma unroll
        for (int s = 0; s < 4; ++s) {
            int fidx = t + 256 * s;          // 0..1023 float4s of W[o][c]
            int o    = fidx >> 4;
            int c4   = fidx & 15;
            float4 w = W4[fidx];
            Wt[(4 * c4 + 0) * WSTR + o] = w.x;
            Wt[(4 * c4 + 1) * WSTR + o] = w.y;
            Wt[(4 * c4 + 2) * WSTR + o] = w.z;
            Wt[(4 * c4 + 3) * WSTR + o] = w.w;
        }
        if (t < COn) bs[t] = bias[t];
    }
    {
        const float* hb = g_h + (size_t)b * 2 * Cn * NT + col0;
#pragma unroll
        for (int s = 0; s < 4; ++s) {
            int idx = t + 256 * s;
            int c   = idx >> 4;
            int v   = idx & 15;
            hs[idx] = ((const float4*)(hb + (size_t)c * NT))[v];
        }
    }
    __syncthreads();

    float4 acc0 = make_float4(bs[4 * oq + 0], bs[4 * oq + 0], bs[4 * oq + 0], bs[4 * oq + 0]);
    float4 acc1 = make_float4(bs[4 * oq + 1], bs[4 * oq + 1], bs[4 * oq + 1], bs[4 * oq + 1]);
    float4 acc2 = make_float4(bs[4 * oq + 2], bs[4 * oq + 2], bs[4 * oq + 2], bs[4 * oq + 2]);
    float4 acc3 = make_float4(bs[4 * oq + 3], bs[4 * oq + 3], bs[4 * oq + 3], bs[4 * oq + 3]);

#pragma unroll 8
    for (int c = 0; c < 2 * Cn; ++c) {
        float4 hv = hs[c * 16 + colq];
        float4 wv = *(const float4*)(Wt + c * WSTR + 4 * oq);
        acc0.x = fmaf(wv.x, hv.x, acc0.x); acc0.y = fmaf(wv.x, hv.y, acc0.y);
        acc0.z = fmaf(wv.x, hv.z, acc0.z); acc0.w = fmaf(wv.x, hv.w, acc0.w);
        acc1.x = fmaf(wv.y, hv.x, acc1.x); acc1.y = fmaf(wv.y, hv.y, acc1.y);
        acc1.z = fmaf(wv.y, hv.z, acc1.z); acc1.w = fmaf(wv.y, hv.w, acc1.w);
        acc2.x = fmaf(wv.z, hv.x, acc2.x); acc2.y = fmaf(wv.z, hv.y, acc2.y);
        acc2.z = fmaf(wv.z, hv.z, acc2.z); acc2.w = fmaf(wv.z, hv.w, acc2.w);
        acc3.x = fmaf(wv.w, hv.x, acc3.x); acc3.y = fmaf(wv.w, hv.y, acc3.y);
        acc3.z = fmaf(wv.w, hv.z, acc3.z); acc3.w = fmaf(wv.w, hv.w, acc3.w);
    }

    float* ob = out + (size_t)b * COn * NT + col0;
    ((float4*)(ob + (size_t)(4 * oq + 0) * NT))[colq] = acc0;
    ((float4*)(ob + (size_t)(4 * oq + 1) * NT))[colq] = acc1;
    ((float4*)(ob + (size_t)(4 * oq + 2) * NT))[colq] = acc2;
    ((float4*)(ob + (size_t)(4 * oq + 3) * NT))[colq] = acc3;
}

// ---------------------------------------------------------------------------
extern "C" void kernel_launch(void* const* d_in, const int* in_sizes, int n_in,
                              void* d_out, int out_size) {
    const float* x    = (const float*)d_in[0];   // [B,C,N,T]
    const float* A    = (const float*)d_in[1];   // [B,C,N,N,T]
    const float* W    = (const float*)d_in[2];   // [C_OUT, 2C]
    const float* bias = (const float*)d_in[3];   // [C_OUT]
    float* out = (float*)d_out;                  // [B,C_OUT,N,T]

    cudaFuncSetAttribute(prop_kernel, cudaFuncAttributeMaxDynamicSharedMemorySize,
                         CACHE_BYTES);

    prop_kernel<<<PROP_CTAS, PROP_THREADS, CACHE_BYTES>>>(x, A);
    mix_kernel<<<Bn * MIX_NCB, 256>>>(W, bias, out);
}

// round 12
// speedup vs baseline: 1.1384x; 1.1384x over previous
#include <cuda_runtime.h>

// Problem constants
#define Bn  16
#define Cn  32
#define Nn  128
#define Tn  12
#define COn 64
#define NT  (Nn * Tn)          // 1536 floats per (b,i,j) row of A
#define NT4 (NT / 4)           // 384 float4
#define NSLICE (Bn * Cn)       // 512 (b,i) slices

// prop config (EXACT R3, proven 92us): 128 persistent CTAs (1/SM via smem
// pad), 768 threads = 4 groups x 192; each group streams 32 of 128 j-rows.
#define PROP_CTAS    128
#define PROP_THREADS 768
#define NGRP 4
#define GSZ  192
#define JPG  (Nn / NGRP)       // 32
#define PROP_PAD (150 * 1024)  // dummy dynamic smem: 36KB static + pad -> 1 CTA/SM

// Scratch: h = concat([x1, x2], channel axis) -> [B][2C][N*T] = 6.3 MB
__device__ float g_h[(size_t)Bn * 2 * Cn * NT];

extern __shared__ char s_pad[];   // occupancy limiter (never accessed)

__device__ __forceinline__ void fma4(float4& acc, const float4 a, const float4 v) {
    acc.x = fmaf(a.x, v.x, acc.x);
    acc.y = fmaf(a.y, v.y, acc.y);
    acc.z = fmaf(a.z, v.z, acc.z);
    acc.w = fmaf(a.w, v.w, acc.w);
}
__device__ __forceinline__ float4 add4(const float4 a, const float4 b) {
    return make_float4(a.x + b.x, a.y + b.y, a.z + b.z, a.w + b.w);
}

// ---------------------------------------------------------------------------
// Kernel 1: fused order-1 + order-2 propagation — EXACT R3 restore.
// Pass 1 streams the slice from HBM (fills L2); pass 2 re-reads from L2
// (last-use). Phase-locked chip-wide footprint 128 x 786KB = 100MB <= 126MB.
// ---------------------------------------------------------------------------
__global__ __launch_bounds__(PROP_THREADS, 1)
void prop_kernel(const float* __restrict__ x, const float* __restrict__ A) {
    __shared__ float4 part[NGRP][NT4];   // 24 KB partial sums
    __shared__ float4 xs[NT4];           // x slice,  [j*3 + lq]
    __shared__ float4 x1s[NT4];          // x1 slice, same layout

    const int t  = threadIdx.x;
    const int g  = t / GSZ;
    const int ti = t - g * GSZ;          // 0..191
    const int lq = ti % 3;
    const int j0 = g * JPG;

    for (int bc = blockIdx.x; bc < NSLICE; bc += PROP_CTAS) {
        const float4* __restrict__ xp = (const float4*)(x + (size_t)bc * NT);
        const float4* __restrict__ Ap = (const float4*)(A + (size_t)bc * Nn * NT);

        if (t < NT4) xs[t] = xp[t];
        __syncthreads();   // also the end-of-previous-iteration barrier

        // ---- Pass 1: x1[k,l] = sum_j x[j,l] * A[j,k,l]  (HBM stream)
        float4 acc0 = make_float4(0.f, 0.f, 0.f, 0.f);
        float4 acc1 = make_float4(0.f, 0.f, 0.f, 0.f);
        {
            const float4* __restrict__ ap = Ap + (size_t)j0 * NT4;
#pragma unroll 4
            for (int jj = 0; jj < JPG; ++jj) {
                float4 a0 = ap[jj * NT4 + ti];
                float4 a1 = ap[jj * NT4 + ti + GSZ];
                float4 xv = xs[(j0 + jj) * 3 + lq];
                fma4(acc0, a0, xv);
                fma4(acc1, a1, xv);
            }
        }
        part[g][ti]       = acc0;
        part[g][ti + GSZ] = acc1;
        __syncthreads();

        // ---- Reduce 1: x1 = sum of 4 partials
        float4 r1;
        if (t < NT4) {
            r1 = add4(add4(part[0][t], part[1][t]), add4(part[2][t], part[3][t]));
            x1s[t] = r1;
        }
        __syncthreads();

        // ---- Pass 2: x2[k,l] = sum_j x1[j,l] * A[j,k,l]  (L2 re-read)
        acc0 = make_float4(0.f, 0.f, 0.f, 0.f);
        acc1 = make_float4(0.f, 0.f, 0.f, 0.f);
        {
            const float4* __restrict__ ap = Ap + (size_t)j0 * NT4;
#pragma unroll 4
            for (int jj = 0; jj < JPG; ++jj) {
                float4 a0 = __ldlu(&ap[jj * NT4 + ti]);
                float4 a1 = __ldlu(&ap[jj * NT4 + ti + GSZ]);
                float4 xv = x1s[(j0 + jj) * 3 + lq];
                fma4(acc0, a0, xv);
                fma4(acc1, a1, xv);
            }
        }
        part[g][ti]       = acc0;
        part[g][ti + GSZ] = acc1;
        __syncthreads();

        // ---- Reduce 2 + write h[b,i,:] = x1, h[b,C+i,:] = x2
        if (t < NT4) {
            float4 r2 = add4(add4(part[0][t], part[1][t]), add4(part[2][t], part[3][t]));
            const int b = bc / Cn;
            const int i = bc % Cn;
            ((float4*)(g_h + ((size_t)b * 2 * Cn + i) * NT))[t]      = r1;
            ((float4*)(g_h + ((size_t)b * 2 * Cn + Cn + i) * NT))[t] = r2;
        }
    }
}

// ---------------------------------------------------------------------------
// Kernel 2: 1x1 conv channel mix, smem-tiled GEMM — same 64x64 tile as the
// proven R3 version, but 512 threads/block (thread = 2 outs x 4 cols).
// Same total instructions; ~2x resident warps per SMSP to hide the 29-cycle
// LDS latency that dominated the 256-thread variant (occ 31%, issue 49%).
// ---------------------------------------------------------------------------
#define MIX_COLS 64
#define MIX_NCB  (NT / MIX_COLS)   // 24

__global__ __launch_bounds__(512) void mix_kernel(const float* __restrict__ W,
                                                  const float* __restrict__ bias,
                                                  float* __restrict__ out) {
    __shared__ float4 hs[(2 * Cn) * (MIX_COLS / 4)];   // 16 KB
    __shared__ float  Ws[COn * 2 * Cn];                // 16 KB
    __shared__ float  bs[COn];

    const int t    = threadIdx.x;                 // 0..511
    const int b    = blockIdx.x / MIX_NCB;
    const int col0 = (blockIdx.x % MIX_NCB) * MIX_COLS;
    const int colq = t & 15;                      // float4 column
    const int oq   = t >> 4;                      // 0..31, owns outs {2oq, 2oq+1}

    {
        float4*       Wd = (float4*)Ws;
        const float4* W4 = (const float4*)W;
#pragma unroll
        for (int s = 0; s < 2; ++s) Wd[t + 512 * s] = W4[t + 512 * s];
        if (t < COn) bs[t] = bias[t];
    }
    {
        const float* hb = g_h + (size_t)b * 2 * Cn * NT + col0;
#pragma unroll
        for (int s = 0; s < 2; ++s) {
            int idx = t + 512 * s;             // 0..1023
            int c   = idx >> 4;
            int v   = idx & 15;
            hs[idx] = ((const float4*)(hb + (size_t)c * NT))[v];
        }
    }
    __syncthreads();

    const int o0 = 2 * oq, o1 = 2 * oq + 1;
    float4 acc0 = make_float4(bs[o0], bs[o0], bs[o0], bs[o0]);
    float4 acc1 = make_float4(bs[o1], bs[o1], bs[o1], bs[o1]);

#pragma unroll 16
    for (int c = 0; c < 2 * Cn; ++c) {
        float4 hv = hs[c * 16 + colq];
        float  w0 = Ws[o0 * 2 * Cn + c];
        float  w1 = Ws[o1 * 2 * Cn + c];
        acc0.x = fmaf(w0, hv.x, acc0.x); acc0.y = fmaf(w0, hv.y, acc0.y);
        acc0.z = fmaf(w0, hv.z, acc0.z); acc0.w = fmaf(w0, hv.w, acc0.w);
        acc1.x = fmaf(w1, hv.x, acc1.x); acc1.y = fmaf(w1, hv.y, acc1.y);
        acc1.z = fmaf(w1, hv.z, acc1.z); acc1.w = fmaf(w1, hv.w, acc1.w);
    }

    float* ob = out + (size_t)b * COn * NT + col0;
    ((float4*)(ob + (size_t)o0 * NT))[colq] = acc0;
    ((float4*)(ob + (size_t)o1 * NT))[colq] = acc1;
}

// ---------------------------------------------------------------------------
extern "C" void kernel_launch(void* const* d_in, const int* in_sizes, int n_in,
                              void* d_out, int out_size) {
    const float* x    = (const float*)d_in[0];   // [B,C,N,T]
    const float* A    = (const float*)d_in[1];   // [B,C,N,N,T]
    const float* W    = (const float*)d_in[2];   // [C_OUT, 2C]
    const float* bias = (const float*)d_in[3];   // [C_OUT]
    float* out = (float*)d_out;                  // [B,C_OUT,N,T]

    cudaFuncSetAttribute(prop_kernel, cudaFuncAttributeMaxDynamicSharedMemorySize, PROP_PAD);

    prop_kernel<<<PROP_CTAS, PROP_THREADS, PROP_PAD>>>(x, A);
    mix_kernel<<<Bn * MIX_NCB, 512>>>(W, bias, out);
}

// round 13
// speedup vs baseline: 1.1387x; 1.0003x over previous
#include <cuda_runtime.h>
#include <cstdint>

// Problem constants
#define Bn  16
#define Cn  32
#define Nn  128
#define Tn  12
#define COn 64
#define NT  (Nn * Tn)          // 1536 floats per (b,i,j) row of A
#define NT4 (NT / 4)           // 384 float4
#define NSLICE (Bn * Cn)       // 512 (b,i) slices

// prop config (EXACT R3 phase): 128 persistent CTAs (1/SM via smem pad),
// 768 threads = 4 groups x 192; each group streams 32 of 128 j-rows.
#define PROP_CTAS    128
#define PROP_THREADS 768
#define NGRP 4
#define GSZ  192
#define JPG  (Nn / NGRP)       // 32
#define PROP_PAD (150 * 1024)  // dynamic smem: occupancy limiter + mix hs buffer

// fused mix epilogue: 1 tile per CTA, tile = 64 outs x 192 cols
#define MIXC  192
#define MIXC4 (MIXC / 4)       // 48
#define TPB   (NT / MIXC)      // 8 tiles per batch; 16*8 = 128 tiles

// Scratch: h = concat([x1, x2], channel axis) -> [B][2C][N*T] = 6.3 MB
__device__ float g_h[(size_t)Bn * 2 * Cn * NT];
// grid barrier counter; zeroed by captured memset before each launch
__device__ unsigned int g_ctr;

extern __shared__ char s_pad[];   // prop: unused pad; mix epilogue: hs (48KB)

__device__ __forceinline__ void fma4(float4& acc, const float4 a, const float4 v) {
    acc.x = fmaf(a.x, v.x, acc.x);
    acc.y = fmaf(a.y, v.y, acc.y);
    acc.z = fmaf(a.z, v.z, acc.z);
    acc.w = fmaf(a.w, v.w, acc.w);
}
__device__ __forceinline__ float4 add4(const float4 a, const float4 b) {
    return make_float4(a.x + b.x, a.y + b.y, a.z + b.z, a.w + b.w);
}
__device__ __forceinline__ unsigned int ld_vol_u32(const unsigned int* p) {
    unsigned int v;
    asm volatile("ld.volatile.global.u32 %0, [%1];" : "=r"(v) : "l"(p));
    return v;
}

// ---------------------------------------------------------------------------
// Single persistent kernel:
// Phase A (EXACT R3 prop): fused order-1/order-2 propagation. Pass 1 streams
//   each slice from HBM (fills L2); pass 2 re-reads from L2 (last-use).
//   Phase-locked footprint 128 x 786KB = 100MB <= 126MB.
// Grid-wide barrier: atomic counter + spin. Safe: 128 CTAs, 1/SM, all
//   co-resident from launch.
// Phase B (mix epilogue): out = W @ h + bias, 1 tile (64 outs x 192 cols)
//   per CTA. h is L2-hot; W loaded once; 24 warps/SM; zero launch overhead.
// ---------------------------------------------------------------------------
__global__ __launch_bounds__(PROP_THREADS, 1)
void fused_kernel(const float* __restrict__ x, const float* __restrict__ A,
                  const float* __restrict__ W, const float* __restrict__ bias,
                  float* __restrict__ out) {
    __shared__ float4 part[NGRP][NT4];   // 24 KB partials; mix: Ws overlay
    __shared__ float4 xs[NT4];           // x slice,  [j*3 + lq]
    __shared__ float4 x1s[NT4];          // x1 slice, same layout
    __shared__ float  bs[COn];

    const int t  = threadIdx.x;
    const int g  = t / GSZ;
    const int ti = t - g * GSZ;          // 0..191
    const int lq = ti % 3;
    const int j0 = g * JPG;

    // ======================= Phase A: propagation (R3) =======================
    for (int bc = blockIdx.x; bc < NSLICE; bc += PROP_CTAS) {
        const float4* __restrict__ xp = (const float4*)(x + (size_t)bc * NT);
        const float4* __restrict__ Ap = (const float4*)(A + (size_t)bc * Nn * NT);

        if (t < NT4) xs[t] = xp[t];
        __syncthreads();   // also the end-of-previous-iteration barrier

        // ---- Pass 1: x1[k,l] = sum_j x[j,l] * A[j,k,l]  (HBM stream)
        float4 acc0 = make_float4(0.f, 0.f, 0.f, 0.f);
        float4 acc1 = make_float4(0.f, 0.f, 0.f, 0.f);
        {
            const float4* __restrict__ ap = Ap + (size_t)j0 * NT4;
#pragma unroll 4
            for (int jj = 0; jj < JPG; ++jj) {
                float4 a0 = ap[jj * NT4 + ti];
                float4 a1 = ap[jj * NT4 + ti + GSZ];
                float4 xv = xs[(j0 + jj) * 3 + lq];
                fma4(acc0, a0, xv);
                fma4(acc1, a1, xv);
            }
        }
        part[g][ti]       = acc0;
        part[g][ti + GSZ] = acc1;
        __syncthreads();

        // ---- Reduce 1: x1 = sum of 4 partials
        float4 r1;
        if (t < NT4) {
            r1 = add4(add4(part[0][t], part[1][t]), add4(part[2][t], part[3][t]));
            x1s[t] = r1;
        }
        __syncthreads();

        // ---- Pass 2: x2[k,l] = sum_j x1[j,l] * A[j,k,l]  (L2 re-read)
        acc0 = make_float4(0.f, 0.f, 0.f, 0.f);
        acc1 = make_float4(0.f, 0.f, 0.f, 0.f);
        {
            const float4* __restrict__ ap = Ap + (size_t)j0 * NT4;
#pragma unroll 4
            for (int jj = 0; jj < JPG; ++jj) {
                float4 a0 = __ldlu(&ap[jj * NT4 + ti]);
                float4 a1 = __ldlu(&ap[jj * NT4 + ti + GSZ]);
                float4 xv = x1s[(j0 + jj) * 3 + lq];
                fma4(acc0, a0, xv);
                fma4(acc1, a1, xv);
            }
        }
        part[g][ti]       = acc0;
        part[g][ti + GSZ] = acc1;
        __syncthreads();

        // ---- Reduce 2 + write h[b,i,:] = x1, h[b,C+i,:] = x2
        if (t < NT4) {
            float4 r2 = add4(add4(part[0][t], part[1][t]), add4(part[2][t], part[3][t]));
            const int b = bc / Cn;
            const int i = bc % Cn;
            ((float4*)(g_h + ((size_t)b * 2 * Cn + i) * NT))[t]      = r1;
            ((float4*)(g_h + ((size_t)b * 2 * Cn + Cn + i) * NT))[t] = r2;
        }
    }

    // ======================= Grid-wide barrier =======================
    __syncthreads();
    if (t == 0) {
        __threadfence();                       // release my h writes
        atomicAdd(&g_ctr, 1u);
        while (ld_vol_u32(&g_ctr) < PROP_CTAS) { }
        __threadfence();                       // acquire others' h writes
    }
    __syncthreads();

    // ======================= Phase B: mix epilogue =======================
    // out[b,o,col] = sum_c W[o,c]*h[b,c,col] + bias[o]
    // CTA -> tile (b = blk/8, cols [192*(blk%8), +192)). Thread (oq=t/48,
    // colq=t%48) computes 4 outs x 4 cols. Inner loop identical to the
    // proven R3 mix: 1 LDS.128 hv + 4 scalar w + 16 FFMA per c.
    {
        float4* hs  = (float4*)s_pad;          // [c][48] float4 = 48 KB
        float*  Wsm = (float*)part;            // 64x64 = 16 KB (of 24 KB)

        const int b    = blockIdx.x >> 3;
        const int col0 = (blockIdx.x & 7) * MIXC;
        const int colq = t % MIXC4;            // 0..47
        const int oq   = t / MIXC4;            // 0..15

        // W: 1024 float4, coalesced
        {
            float4*       Wd = (float4*)Wsm;
            const float4* W4 = (const float4*)W;
            for (int s = t; s < 1024; s += PROP_THREADS) Wd[s] = W4[s];
            if (t < COn) bs[t] = bias[t];
        }
        // h tile: 64 c x 48 float4, coalesced per channel row (L2-hot)
        {
            const float* hb = g_h + (size_t)b * 2 * Cn * NT + col0;
            for (int s = t; s < 2 * Cn * MIXC4; s += PROP_THREADS) {
                int c = s / MIXC4;
                int v = s % MIXC4;
                hs[s] = ((const float4*)(hb + (size_t)c * NT))[v];
            }
        }
        __syncthreads();

        float4 acc0 = make_float4(bs[4 * oq + 0], bs[4 * oq + 0], bs[4 * oq + 0], bs[4 * oq + 0]);
        float4 acc1 = make_float4(bs[4 * oq + 1], bs[4 * oq + 1], bs[4 * oq + 1], bs[4 * oq + 1]);
        float4 acc2 = make_float4(bs[4 * oq + 2], bs[4 * oq + 2], bs[4 * oq + 2], bs[4 * oq + 2]);
        float4 acc3 = make_float4(bs[4 * oq + 3], bs[4 * oq + 3], bs[4 * oq + 3], bs[4 * oq + 3]);

#pragma unroll 8
        for (int c = 0; c < 2 * Cn; ++c) {
            float4 hv = hs[c * MIXC4 + colq];
            float  w0 = Wsm[(4 * oq + 0) * 2 * Cn + c];
            float  w1 = Wsm[(4 * oq + 1) * 2 * Cn + c];
            float  w2 = Wsm[(4 * oq + 2) * 2 * Cn + c];
            float  w3 = Wsm[(4 * oq + 3) * 2 * Cn + c];
            acc0.x = fmaf(w0, hv.x, acc0.x); acc0.y = fmaf(w0, hv.y, acc0.y);
            acc0.z = fmaf(w0, hv.z, acc0.z); acc0.w = fmaf(w0, hv.w, acc0.w);
            acc1.x = fmaf(w1, hv.x, acc1.x); acc1.y = fmaf(w1, hv.y, acc1.y);
            acc1.z = fmaf(w1, hv.z, acc1.z); acc1.w = fmaf(w1, hv.w, acc1.w);
            acc2.x = fmaf(w2, hv.x, acc2.x); acc2.y = fmaf(w2, hv.y, acc2.y);
            acc2.z = fmaf(w2, hv.z, acc2.z); acc2.w = fmaf(w2, hv.w, acc2.w);
            acc3.x = fmaf(w3, hv.x, acc3.x); acc3.y = fmaf(w3, hv.y, acc3.y);
            acc3.z = fmaf(w3, hv.z, acc3.z); acc3.w = fmaf(w3, hv.w, acc3.w);
        }

        float* ob = out + (size_t)b * COn * NT + col0;
        ((float4*)(ob + (size_t)(4 * oq + 0) * NT))[colq] = acc0;
        ((float4*)(ob + (size_t)(4 * oq + 1) * NT))[colq] = acc1;
        ((float4*)(ob + (size_t)(4 * oq + 2) * NT))[colq] = acc2;
        ((float4*)(ob + (size_t)(4 * oq + 3) * NT))[colq] = acc3;
    }
}

// ---------------------------------------------------------------------------
extern "C" void kernel_launch(void* const* d_in, const int* in_sizes, int n_in,
                              void* d_out, int out_size) {
    const float* x    = (const float*)d_in[0];   // [B,C,N,T]
    const float* A    = (const float*)d_in[1];   // [B,C,N,N,T]
    const float* W    = (const float*)d_in[2];   // [C_OUT, 2C]
    const float* bias = (const float*)d_in[3];   // [C_OUT]
    float* out = (float*)d_out;                  // [B,C_OUT,N,T]

    // reset the grid-barrier counter each replay (captured memset node)
    void* cp = nullptr;
    cudaGetSymbolAddress(&cp, g_ctr);
    cudaMemsetAsync(cp, 0, sizeof(unsigned int));

    cudaFuncSetAttribute(fused_kernel, cudaFuncAttributeMaxDynamicSharedMemorySize,
                         PROP_PAD);

    fused_kernel<<<PROP_CTAS, PROP_THREADS, PROP_PAD>>>(x, A, W, bias, out);
}